// round 15
// baseline (speedup 1.0000x reference)
#include <cuda_runtime.h>
#include <cuda_bf16.h>
#include <math.h>

// Problem constants
#define H   1024
#define H2  2048
#define H3  3072
#define S   4096
#define V   50257

// Output layout (tuple order: output[V], context[H], new_hidden[2H], attn_w[S])
#define OUT_LOGP 0
#define OUT_CTX  (V)
#define OUT_NEWH (V + H)
#define OUT_ATTN (V + 3 * H)

// Logits kernel geometry (best measured variant)
#define LOG_ROWS_PER_BLK 16
#define NB_LOGITS ((V + LOG_ROWS_PER_BLK - 1) / LOG_ROWS_PER_BLK)   // 3142

// Attention kernel grid
#define ATT_NB 512

// ---------------- scratch (device globals; no allocation allowed) -----------
__device__ float g_a[H3], g_b[H3], g_c[H3];   // gates0 partials (gi0 = a+b, gh0 = c)
__device__ float g_gi1[H3], g_gh1[H3];
__device__ float g_h1[H];
__device__ float g_v[H];
__device__ float g_ctx[H];
__device__ float g_energ[S];
__device__ float g_logits[V + 16];
__device__ float g_pm[NB_LOGITS + 16], g_ps[NB_LOGITS + 16];
__device__ float g_L;           // final log-sum-exp scalar
__device__ unsigned g_bar[4];   // monotone grid-barrier counters (never reset)
__device__ unsigned g_cnt;      // logits last-block ticket (atomicInc wraps -> self-reset)

// ---------------- helpers ---------------------------------------------------
__device__ __forceinline__ float sigm(float x) { return 1.0f / (1.0f + expf(-x)); }

// Full-unroll dot (logits only: long-running multi-wave kernel where
// front-batched loads maximize BW and spread amortizes).
template <int K>
__device__ __forceinline__ float warp_dot_cs(const float* __restrict__ w,
                                             const float* __restrict__ x, int lane) {
    float a0 = 0.f, a1 = 0.f, a2 = 0.f, a3 = 0.f;
#pragma unroll
    for (int k0 = 0; k0 < K; k0 += 128) {
        int k = k0 + lane * 4;
        float4 f = __ldcs(reinterpret_cast<const float4*>(w + k));
        float4 xv = *reinterpret_cast<const float4*>(x + k);
        a0 += f.x * xv.x; a1 += f.y * xv.y; a2 += f.z * xv.z; a3 += f.w * xv.w;
    }
    float acc = (a0 + a1) + (a2 + a3);
#pragma unroll
    for (int o = 16; o; o >>= 1) acc += __shfl_down_sync(0xffffffffu, acc, o);
    return acc;
}

// Unroll-2 dots for front-chain kernels: MLP_p1 = 2 keeps the cross-CTA
// L1tex-queue spread near its floor (straggler control at barriers) while
// still providing enough in-flight bytes for full DRAM bandwidth.
template <int K>
__device__ __forceinline__ float warp_dot_cs_u2(const float* __restrict__ w,
                                                const float* __restrict__ x, int lane) {
    float a0 = 0.f, a1 = 0.f, a2 = 0.f, a3 = 0.f;
#pragma unroll 2
    for (int k0 = 0; k0 < K; k0 += 128) {
        int k = k0 + lane * 4;
        float4 f = __ldcs(reinterpret_cast<const float4*>(w + k));
        float4 xv = *reinterpret_cast<const float4*>(x + k);
        a0 += f.x * xv.x; a1 += f.y * xv.y; a2 += f.z * xv.z; a3 += f.w * xv.w;
    }
    float acc = (a0 + a1) + (a2 + a3);
#pragma unroll
    for (int o = 16; o; o >>= 1) acc += __shfl_down_sync(0xffffffffu, acc, o);
    return acc;
}

// Same, default cache policy (enc: keep L2-resident for the context phase).
template <int K>
__device__ __forceinline__ float warp_dot_u2(const float* __restrict__ w,
                                             const float* __restrict__ x, int lane) {
    float a0 = 0.f, a1 = 0.f, a2 = 0.f, a3 = 0.f;
#pragma unroll 2
    for (int k0 = 0; k0 < K; k0 += 128) {
        int k = k0 + lane * 4;
        float4 f = *reinterpret_cast<const float4*>(w + k);
        float4 xv = *reinterpret_cast<const float4*>(x + k);
        a0 += f.x * xv.x; a1 += f.y * xv.y; a2 += f.z * xv.z; a3 += f.w * xv.w;
    }
    float acc = (a0 + a1) + (a2 + a3);
#pragma unroll
    for (int o = 16; o; o >>= 1) acc += __shfl_down_sync(0xffffffffu, acc, o);
    return acc;
}

// Grid-wide barrier among the first NB blocks, monotone counter (replay-safe).
__device__ __forceinline__ void grid_barrier(int k, unsigned NB) {
    __threadfence();
    __syncthreads();
    if (threadIdx.x == 0) {
        unsigned t = atomicAdd(&g_bar[k], 1u);
        unsigned target = (t / NB + 1u) * NB;
        while (*(volatile unsigned*)&g_bar[k] < target) __nanosleep(64);
    }
    __syncthreads();
    __threadfence();
}

// h0 from gates0 partials (bias folded here; gi0 = a+b, gh0 = c)
__device__ __forceinline__ float h0_combine(const float* __restrict__ bih0,
                                            const float* __restrict__ bhh0,
                                            const float* __restrict__ hid, int j) {
    float gr = g_a[j] + g_b[j] + bih0[j];
    float gz = g_a[H + j] + g_b[H + j] + bih0[H + j];
    float gn = g_a[2 * H + j] + g_b[2 * H + j] + bih0[2 * H + j];
    float hr = g_c[j] + bhh0[j];
    float hz = g_c[H + j] + bhh0[H + j];
    float hn = g_c[2 * H + j] + bhh0[2 * H + j];
    float r = sigm(gr + hr);
    float z = sigm(gz + hz);
    float n = tanhf(gn + r * hn);
    return (1.0f - z) * n + z * hid[j];
}

// h1 from gates1 results (biases already added)
__device__ __forceinline__ float h1_combine(const float* __restrict__ hid1, int j) {
    float r = sigm(g_gi1[j] + g_gh1[j]);
    float z = sigm(g_gi1[H + j] + g_gh1[H + j]);
    float n = tanhf(g_gi1[2 * H + j] + r * g_gh1[2 * H + j]);
    return (1.0f - z) * n + z * hid1[j];
}

// ---------------- K1: GRU0 gate matvecs, K-split (1152 blocks) ---------------
// blocks [0,384):    g_a[row] = Wih0[row][0:H]   . emb[tok]
// blocks [384,768):  g_b[row] = Wih0[row][H:2H]  . last_context
// blocks [768,1152): g_c[row] = Whh0[row]        . hidden[0]
// Biases folded at the consumer (h0_combine).
__global__ __launch_bounds__(256) void k_gates0(
        const int* __restrict__ tok, const float* __restrict__ lastctx,
        const float* __restrict__ hid, const float* __restrict__ emb,
        const float* __restrict__ Wih0, const float* __restrict__ Whh0) {
    __shared__ __align__(16) float sx[H];
    int b = blockIdx.x;
    int grp = b / 384, rb = b % 384;
    if (grp == 0) {
        int t = tok[0];
        for (int j = threadIdx.x; j < H; j += 256) sx[j] = emb[(size_t)t * H + j];
    } else if (grp == 1) {
        for (int j = threadIdx.x; j < H; j += 256) sx[j] = lastctx[j];
    } else {
        for (int j = threadIdx.x; j < H; j += 256) sx[j] = hid[j];
    }
    __syncthreads();
    int w = threadIdx.x >> 5, lane = threadIdx.x & 31;
    int row = rb * 8 + w;
    if (grp == 0) {
        float d = warp_dot_cs_u2<H>(Wih0 + (size_t)row * H2, sx, lane);
        if (lane == 0) g_a[row] = d;
    } else if (grp == 1) {
        float d = warp_dot_cs_u2<H>(Wih0 + (size_t)row * H2 + H, sx, lane);
        if (lane == 0) g_b[row] = d;
    } else {
        float d = warp_dot_cs_u2<H>(Whh0 + (size_t)row * H, sx, lane);
        if (lane == 0) g_c[row] = d;
    }
}

// ---------------- K2: combine h0 + GRU1 gate matvecs (768 blocks) ------------
__global__ __launch_bounds__(256) void k_gates1(
        const float* __restrict__ hid,
        const float* __restrict__ bih0, const float* __restrict__ bhh0,
        const float* __restrict__ Wih1, const float* __restrict__ bih1,
        const float* __restrict__ Whh1, const float* __restrict__ bhh1,
        float* __restrict__ out) {
    __shared__ __align__(16) float sx[H];
    int b = blockIdx.x;
    bool is_gi = (b < 384);
    if (is_gi) {
        for (int j = threadIdx.x; j < H; j += 256)
            sx[j] = h0_combine(bih0, bhh0, hid, j);
    } else {
        for (int j = threadIdx.x; j < H; j += 256) sx[j] = hid[H + j];
    }
    __syncthreads();
    if (b == 0) {
        for (int j = threadIdx.x; j < H; j += 256) {
            out[OUT_NEWH + j] = sx[j];   // new_hidden[0]
            g_v[j] = 0.0f;               // zero for attnv atomics
            g_ctx[j] = 0.0f;             // zero for context atomics
        }
    }
    int w = threadIdx.x >> 5, lane = threadIdx.x & 31;
    if (is_gi) {
        int row = b * 8 + w;
        float d = warp_dot_cs_u2<H>(Wih1 + (size_t)row * H, sx, lane);
        if (lane == 0) g_gi1[row] = d + bih1[row];
    } else {
        int row = (b - 384) * 8 + w;
        float d = warp_dot_cs_u2<H>(Whh1 + (size_t)row * H, sx, lane);
        if (lane == 0) g_gh1[row] = d + bhh1[row];
    }
}

// ---------------- K3: attention mega-kernel (512 blocks x 256, 3 phases) -----
// Phase A: blocks<128 rebuild h1; blocks<64 do v = h1 @ attn_W (atomics);
//          block 0 publishes h1 + new_hidden[1].                 [barrier 0]
// Phase B: energies = enc @ v, warp-per-row (512*8 = 4096 rows). [barrier 1]
// Phase C: each block redundantly reduces softmax stats over S (L2-hot),
//          then context = attn @ enc (32-row chunks x 4 col groups, atomics);
//          colg==0 blocks write the attn_w output rows.
// attn_b folds into a softmax-invariant constant and is dropped.
__global__ __launch_bounds__(256) void k_attention(const float* __restrict__ hid,
                                                   const float* __restrict__ attnW,
                                                   const float* __restrict__ enc,
                                                   float* __restrict__ out) {
    __shared__ __align__(16) float sbuf[H];
    __shared__ float sred[8];
    __shared__ float sw[32];
    int tid = threadIdx.x, b = blockIdx.x;
    int w = tid >> 5, lane = tid & 31;

    // ---- Phase A: h1 rebuild (blocks < 128) + attnv (blocks < 64) ----
    if (b < 128) {
        for (int j = tid; j < H; j += 256) sbuf[j] = h1_combine(hid + H, j);
        __syncthreads();
        if (b == 0) {
            for (int j = tid; j < H; j += 256) {
                out[OUT_NEWH + H + j] = sbuf[j];   // new_hidden[1]
                g_h1[j] = sbuf[j];
            }
        }
        if (b < 64) {
            int colg = b & 3, rowc = b >> 2;
            int col = colg * 256 + tid;
            int j0 = rowc * 64;
            float acc = 0.f;
#pragma unroll 8
            for (int j = j0; j < j0 + 64; ++j)
                acc += attnW[(size_t)j * H + col] * sbuf[j];
            atomicAdd(&g_v[col], acc);
        }
    }
    grid_barrier(0, ATT_NB);

    // ---- Phase B: energies (default-policy loads keep enc L2-hot) ----
    for (int j = tid; j < H; j += 256) sbuf[j] = g_v[j];
    __syncthreads();
    {
        int row = b * 8 + w;
        float d = warp_dot_u2<H>(enc + (size_t)row * H, sbuf, lane);
        if (lane == 0) g_energ[row] = d;
    }
    grid_barrier(1, ATT_NB);

    // ---- Phase C: redundant softmax stats + context (merged) ----
    {
        float e[16];
        float m = -1e30f;
#pragma unroll
        for (int i = 0; i < 16; i++) { e[i] = g_energ[tid + i * 256]; m = fmaxf(m, e[i]); }
#pragma unroll
        for (int o = 16; o; o >>= 1) m = fmaxf(m, __shfl_xor_sync(0xffffffffu, m, o));
        if (lane == 0) sred[w] = m;
        __syncthreads();
        if (tid < 8) {
            float v = sred[tid];
#pragma unroll
            for (int o = 4; o; o >>= 1) v = fmaxf(v, __shfl_xor_sync(0xffu, v, o));
            if (tid == 0) sred[0] = v;
        }
        __syncthreads();
        float M = sred[0];
        __syncthreads();
        float s = 0.f;
#pragma unroll
        for (int i = 0; i < 16; i++) s += expf(e[i] - M);
#pragma unroll
        for (int o = 16; o; o >>= 1) s += __shfl_xor_sync(0xffffffffu, s, o);
        if (lane == 0) sred[w] = s;
        __syncthreads();
        if (tid < 8) {
            float v = sred[tid];
#pragma unroll
            for (int o = 4; o; o >>= 1) v += __shfl_xor_sync(0xffu, v, o);
            if (tid == 0) sred[0] = v;
        }
        __syncthreads();
        float inv = 1.0f / sred[0];

        int colg = b & 3, rowc = b >> 2;   // rowc in [0,128): 32-row chunks
        if (tid < 32) {
            float wv = expf(g_energ[rowc * 32 + tid] - M) * inv;
            sw[tid] = wv;
            if (colg == 0) out[OUT_ATTN + rowc * 32 + tid] = wv;
        }
        __syncthreads();
        int col = colg * 256 + tid;
        const float* base = enc + (size_t)(rowc * 32) * H + col;
        float acc = 0.f;
#pragma unroll 8
        for (int j = 0; j < 32; ++j) acc += sw[j] * base[(size_t)j * H];
        atomicAdd(&g_ctx[col], acc);
    }
}

// ---------------- K4: logits + fused LSE tail (3142 blocks x 512) ------------
// Per-block (max,sumexp) partial; the LAST-finishing block (self-wrapping
// atomicInc ticket, resets across graph replays) reduces all 3142 partials
// once and publishes the scalar g_L = M + log(sum).
__global__ __launch_bounds__(512) void k_logits(const float* __restrict__ outW,
                                                const float* __restrict__ outb,
                                                float* __restrict__ out) {
    __shared__ __align__(16) float sx[H2];
    __shared__ float srow[16];
    __shared__ unsigned s_last;
    int tid = threadIdx.x;
    for (int j = tid; j < H2; j += 512)
        sx[j] = (j < H) ? g_h1[j] : g_ctx[j - H];
    __syncthreads();
    if (blockIdx.x == 0) {
        for (int j = tid; j < H; j += 512) out[OUT_CTX + j] = g_ctx[j];
    }
    int w = tid >> 5, lane = tid & 31;
    int row = blockIdx.x * LOG_ROWS_PER_BLK + w;
    float logit = -1e30f;
    if (row < V) {
        float d = warp_dot_cs<H2>(outW + (size_t)row * H2, sx, lane);
        if (lane == 0) {
            logit = d + outb[row];
            g_logits[row] = logit;
        }
    }
    if (lane == 0) srow[w] = logit;
    __syncthreads();
    if (tid == 0) {
        float m = -1e30f;
#pragma unroll
        for (int i = 0; i < 16; i++) m = fmaxf(m, srow[i]);
        float s = 0.f;
#pragma unroll
        for (int i = 0; i < 16; i++) s += expf(srow[i] - m);
        g_pm[blockIdx.x] = m;
        g_ps[blockIdx.x] = s;
    }
    // ---- last-block LSE reduction ----
    __threadfence();
    __syncthreads();
    if (tid == 0)
        s_last = (atomicInc(&g_cnt, gridDim.x - 1) == gridDim.x - 1);
    __syncthreads();
    if (!s_last) return;
    __threadfence();
    {
        __shared__ float sred2[16];
        float m = -1e30f;
        for (int i = tid; i < NB_LOGITS; i += 512) m = fmaxf(m, g_pm[i]);
#pragma unroll
        for (int o = 16; o; o >>= 1) m = fmaxf(m, __shfl_xor_sync(0xffffffffu, m, o));
        if (lane == 0) sred2[w] = m;
        __syncthreads();
        if (tid < 16) {
            float v = sred2[tid];
#pragma unroll
            for (int o = 8; o; o >>= 1) v = fmaxf(v, __shfl_xor_sync(0xffffu, v, o));
            if (tid == 0) sred2[0] = v;
        }
        __syncthreads();
        float M = sred2[0];
        __syncthreads();
        float s = 0.f;
        for (int i = tid; i < NB_LOGITS; i += 512) s += g_ps[i] * expf(g_pm[i] - M);
#pragma unroll
        for (int o = 16; o; o >>= 1) s += __shfl_xor_sync(0xffffffffu, s, o);
        if (lane == 0) sred2[w] = s;
        __syncthreads();
        if (tid < 16) {
            float v = sred2[tid];
#pragma unroll
            for (int o = 8; o; o >>= 1) v += __shfl_xor_sync(0xffffu, v, o);
            if (tid == 0) g_L = M + logf(v);
        }
    }
}

// ---------------- K5: final write (99 blocks x 512; pure stream) -------------
__global__ __launch_bounds__(512) void k_final(float* __restrict__ out) {
    float L = g_L;   // scalar broadcast (L2)
    int idx = blockIdx.x * 512 + threadIdx.x;
    if (idx < V) out[OUT_LOGP + idx] = g_logits[idx] - L;
}

// ---------------- launch -----------------------------------------------------
extern "C" void kernel_launch(void* const* d_in, const int* in_sizes, int n_in,
                              void* d_out, int out_size) {
    const int*   tok     = (const int*)d_in[0];
    const float* lastctx = (const float*)d_in[1];
    const float* hid     = (const float*)d_in[2];
    const float* enc     = (const float*)d_in[3];
    const float* emb     = (const float*)d_in[4];
    const float* attnW   = (const float*)d_in[5];
    // d_in[6] = attn_b: softmax-invariant, dropped.
    const float* Wih0    = (const float*)d_in[7];
    const float* Whh0    = (const float*)d_in[8];
    const float* bih0    = (const float*)d_in[9];
    const float* bhh0    = (const float*)d_in[10];
    const float* Wih1    = (const float*)d_in[11];
    const float* Whh1    = (const float*)d_in[12];
    const float* bih1    = (const float*)d_in[13];
    const float* bhh1    = (const float*)d_in[14];
    const float* outW    = (const float*)d_in[15];
    const float* outb    = (const float*)d_in[16];
    float* out = (float*)d_out;

    k_gates0   <<<1152, 256>>>(tok, lastctx, hid, emb, Wih0, Whh0);
    k_gates1   <<<768, 256>>>(hid, bih0, bhh0, Wih1, bih1, Whh1, bhh1, out);
    k_attention<<<ATT_NB, 256>>>(hid, attnW, enc, out);
    k_logits   <<<NB_LOGITS, 512>>>(outW, outb, out);   // launch #4 -> profiled
    k_final    <<<(V + 511) / 512, 512>>>(out);
}

// round 16
// speedup vs baseline: 1.0403x; 1.0403x over previous
#include <cuda_runtime.h>
#include <cuda_bf16.h>
#include <math.h>

// Problem constants
#define H   1024
#define H2  2048
#define H3  3072
#define S   4096
#define V   50257

// Output layout (tuple order: output[V], context[H], new_hidden[2H], attn_w[S])
#define OUT_LOGP 0
#define OUT_CTX  (V)
#define OUT_NEWH (V + H)
#define OUT_ATTN (V + 3 * H)

// Logits kernel geometry (best measured variant)
#define LOG_ROWS_PER_BLK 16
#define NB_LOGITS ((V + LOG_ROWS_PER_BLK - 1) / LOG_ROWS_PER_BLK)   // 3142

// Attention kernel grid
#define ATT_NB 512

// ---------------- scratch (device globals; no allocation allowed) -----------
__device__ float g_a[H3], g_b[H3], g_c[H3];   // gates0 partials (gi0 = a+b, gh0 = c)
__device__ float g_gi1[H3], g_gh1[H3];
__device__ float g_h1[H];
__device__ float g_v[H];
__device__ float g_ctx[H];
__device__ float g_energ[S];
__device__ float g_logits[V + 16];
__device__ float g_pm[NB_LOGITS + 16], g_ps[NB_LOGITS + 16];
__device__ unsigned g_bar[4];   // monotone grid-barrier counters (never reset)

// ---------------- helpers ---------------------------------------------------
__device__ __forceinline__ float sigm(float x) { return 1.0f / (1.0f + expf(-x)); }

// Full-unroll dot (logits only: long-running multi-wave kernel where
// front-batched loads maximize BW and spread amortizes).
template <int K>
__device__ __forceinline__ float warp_dot_cs(const float* __restrict__ w,
                                             const float* __restrict__ x, int lane) {
    float a0 = 0.f, a1 = 0.f, a2 = 0.f, a3 = 0.f;
#pragma unroll
    for (int k0 = 0; k0 < K; k0 += 128) {
        int k = k0 + lane * 4;
        float4 f = __ldcs(reinterpret_cast<const float4*>(w + k));
        float4 xv = *reinterpret_cast<const float4*>(x + k);
        a0 += f.x * xv.x; a1 += f.y * xv.y; a2 += f.z * xv.z; a3 += f.w * xv.w;
    }
    float acc = (a0 + a1) + (a2 + a3);
#pragma unroll
    for (int o = 16; o; o >>= 1) acc += __shfl_down_sync(0xffffffffu, acc, o);
    return acc;
}

// Unroll-2 dots for front-chain kernels: MLP_p1 = 2 keeps the cross-CTA
// L1tex-queue spread near its floor (straggler control at barriers) while
// still providing enough in-flight bytes for full DRAM bandwidth.
template <int K>
__device__ __forceinline__ float warp_dot_cs_u2(const float* __restrict__ w,
                                                const float* __restrict__ x, int lane) {
    float a0 = 0.f, a1 = 0.f, a2 = 0.f, a3 = 0.f;
#pragma unroll 2
    for (int k0 = 0; k0 < K; k0 += 128) {
        int k = k0 + lane * 4;
        float4 f = __ldcs(reinterpret_cast<const float4*>(w + k));
        float4 xv = *reinterpret_cast<const float4*>(x + k);
        a0 += f.x * xv.x; a1 += f.y * xv.y; a2 += f.z * xv.z; a3 += f.w * xv.w;
    }
    float acc = (a0 + a1) + (a2 + a3);
#pragma unroll
    for (int o = 16; o; o >>= 1) acc += __shfl_down_sync(0xffffffffu, acc, o);
    return acc;
}

// Same, default cache policy (enc: keep L2-resident for the context phase).
template <int K>
__device__ __forceinline__ float warp_dot_u2(const float* __restrict__ w,
                                             const float* __restrict__ x, int lane) {
    float a0 = 0.f, a1 = 0.f, a2 = 0.f, a3 = 0.f;
#pragma unroll 2
    for (int k0 = 0; k0 < K; k0 += 128) {
        int k = k0 + lane * 4;
        float4 f = *reinterpret_cast<const float4*>(w + k);
        float4 xv = *reinterpret_cast<const float4*>(x + k);
        a0 += f.x * xv.x; a1 += f.y * xv.y; a2 += f.z * xv.z; a3 += f.w * xv.w;
    }
    float acc = (a0 + a1) + (a2 + a3);
#pragma unroll
    for (int o = 16; o; o >>= 1) acc += __shfl_down_sync(0xffffffffu, acc, o);
    return acc;
}

// Grid-wide barrier among the first NB blocks, monotone counter (replay-safe).
__device__ __forceinline__ void grid_barrier(int k, unsigned NB) {
    __threadfence();
    __syncthreads();
    if (threadIdx.x == 0) {
        unsigned t = atomicAdd(&g_bar[k], 1u);
        unsigned target = (t / NB + 1u) * NB;
        while (*(volatile unsigned*)&g_bar[k] < target) __nanosleep(64);
    }
    __syncthreads();
    __threadfence();
}

// h0 from gates0 partials (bias folded here; gi0 = a+b, gh0 = c)
__device__ __forceinline__ float h0_combine(const float* __restrict__ bih0,
                                            const float* __restrict__ bhh0,
                                            const float* __restrict__ hid, int j) {
    float gr = g_a[j] + g_b[j] + bih0[j];
    float gz = g_a[H + j] + g_b[H + j] + bih0[H + j];
    float gn = g_a[2 * H + j] + g_b[2 * H + j] + bih0[2 * H + j];
    float hr = g_c[j] + bhh0[j];
    float hz = g_c[H + j] + bhh0[H + j];
    float hn = g_c[2 * H + j] + bhh0[2 * H + j];
    float r = sigm(gr + hr);
    float z = sigm(gz + hz);
    float n = tanhf(gn + r * hn);
    return (1.0f - z) * n + z * hid[j];
}

// h1 from gates1 results (biases already added)
__device__ __forceinline__ float h1_combine(const float* __restrict__ hid1, int j) {
    float r = sigm(g_gi1[j] + g_gh1[j]);
    float z = sigm(g_gi1[H + j] + g_gh1[H + j]);
    float n = tanhf(g_gi1[2 * H + j] + r * g_gh1[2 * H + j]);
    return (1.0f - z) * n + z * hid1[j];
}

// ---------------- K1: GRU0 gate matvecs, K-split (1152 blocks) ---------------
// blocks [0,384):    g_a[row] = Wih0[row][0:H]   . emb[tok]
// blocks [384,768):  g_b[row] = Wih0[row][H:2H]  . last_context
// blocks [768,1152): g_c[row] = Whh0[row]        . hidden[0]
// Biases folded at the consumer (h0_combine).
__global__ __launch_bounds__(256) void k_gates0(
        const int* __restrict__ tok, const float* __restrict__ lastctx,
        const float* __restrict__ hid, const float* __restrict__ emb,
        const float* __restrict__ Wih0, const float* __restrict__ Whh0) {
    __shared__ __align__(16) float sx[H];
    int b = blockIdx.x;
    int grp = b / 384, rb = b % 384;
    if (grp == 0) {
        int t = tok[0];
        for (int j = threadIdx.x; j < H; j += 256) sx[j] = emb[(size_t)t * H + j];
    } else if (grp == 1) {
        for (int j = threadIdx.x; j < H; j += 256) sx[j] = lastctx[j];
    } else {
        for (int j = threadIdx.x; j < H; j += 256) sx[j] = hid[j];
    }
    __syncthreads();
    int w = threadIdx.x >> 5, lane = threadIdx.x & 31;
    int row = rb * 8 + w;
    if (grp == 0) {
        float d = warp_dot_cs_u2<H>(Wih0 + (size_t)row * H2, sx, lane);
        if (lane == 0) g_a[row] = d;
    } else if (grp == 1) {
        float d = warp_dot_cs_u2<H>(Wih0 + (size_t)row * H2 + H, sx, lane);
        if (lane == 0) g_b[row] = d;
    } else {
        float d = warp_dot_cs_u2<H>(Whh0 + (size_t)row * H, sx, lane);
        if (lane == 0) g_c[row] = d;
    }
}

// ---------------- K2: combine h0 + GRU1 gate matvecs (768 blocks) ------------
__global__ __launch_bounds__(256) void k_gates1(
        const float* __restrict__ hid,
        const float* __restrict__ bih0, const float* __restrict__ bhh0,
        const float* __restrict__ Wih1, const float* __restrict__ bih1,
        const float* __restrict__ Whh1, const float* __restrict__ bhh1,
        float* __restrict__ out) {
    __shared__ __align__(16) float sx[H];
    int b = blockIdx.x;
    bool is_gi = (b < 384);
    if (is_gi) {
        for (int j = threadIdx.x; j < H; j += 256)
            sx[j] = h0_combine(bih0, bhh0, hid, j);
    } else {
        for (int j = threadIdx.x; j < H; j += 256) sx[j] = hid[H + j];
    }
    __syncthreads();
    if (b == 0) {
        for (int j = threadIdx.x; j < H; j += 256) {
            out[OUT_NEWH + j] = sx[j];   // new_hidden[0]
            g_v[j] = 0.0f;               // zero for attnv atomics
            g_ctx[j] = 0.0f;             // zero for context atomics
        }
    }
    int w = threadIdx.x >> 5, lane = threadIdx.x & 31;
    if (is_gi) {
        int row = b * 8 + w;
        float d = warp_dot_cs_u2<H>(Wih1 + (size_t)row * H, sx, lane);
        if (lane == 0) g_gi1[row] = d + bih1[row];
    } else {
        int row = (b - 384) * 8 + w;
        float d = warp_dot_cs_u2<H>(Whh1 + (size_t)row * H, sx, lane);
        if (lane == 0) g_gh1[row] = d + bhh1[row];
    }
}

// ---------------- K3: attention mega-kernel (512 blocks x 256, 3 phases) -----
// Phase A: blocks<128 rebuild h1; blocks<64 do v = h1 @ attn_W (atomics);
//          block 0 publishes h1 + new_hidden[1].                 [barrier 0]
// Phase B: energies = enc @ v, warp-per-row (512*8 = 4096 rows). [barrier 1]
// Phase C: each block redundantly reduces softmax stats over S (L2-hot),
//          then context = attn @ enc (32-row chunks x 4 col groups, atomics);
//          colg==0 blocks write the attn_w output rows.
// attn_b folds into a softmax-invariant constant and is dropped.
__global__ __launch_bounds__(256) void k_attention(const float* __restrict__ hid,
                                                   const float* __restrict__ attnW,
                                                   const float* __restrict__ enc,
                                                   float* __restrict__ out) {
    __shared__ __align__(16) float sbuf[H];
    __shared__ float sred[8];
    __shared__ float sw[32];
    int tid = threadIdx.x, b = blockIdx.x;
    int w = tid >> 5, lane = tid & 31;

    // ---- Phase A: h1 rebuild (blocks < 128) + attnv (blocks < 64) ----
    if (b < 128) {
        for (int j = tid; j < H; j += 256) sbuf[j] = h1_combine(hid + H, j);
        __syncthreads();
        if (b == 0) {
            for (int j = tid; j < H; j += 256) {
                out[OUT_NEWH + H + j] = sbuf[j];   // new_hidden[1]
                g_h1[j] = sbuf[j];
            }
        }
        if (b < 64) {
            int colg = b & 3, rowc = b >> 2;
            int col = colg * 256 + tid;
            int j0 = rowc * 64;
            float acc = 0.f;
#pragma unroll 8
            for (int j = j0; j < j0 + 64; ++j)
                acc += attnW[(size_t)j * H + col] * sbuf[j];
            atomicAdd(&g_v[col], acc);
        }
    }
    grid_barrier(0, ATT_NB);

    // ---- Phase B: energies (default-policy loads keep enc L2-hot) ----
    for (int j = tid; j < H; j += 256) sbuf[j] = g_v[j];
    __syncthreads();
    {
        int row = b * 8 + w;
        float d = warp_dot_u2<H>(enc + (size_t)row * H, sbuf, lane);
        if (lane == 0) g_energ[row] = d;
    }
    grid_barrier(1, ATT_NB);

    // ---- Phase C: redundant softmax stats + context (merged) ----
    {
        float e[16];
        float m = -1e30f;
#pragma unroll
        for (int i = 0; i < 16; i++) { e[i] = g_energ[tid + i * 256]; m = fmaxf(m, e[i]); }
#pragma unroll
        for (int o = 16; o; o >>= 1) m = fmaxf(m, __shfl_xor_sync(0xffffffffu, m, o));
        if (lane == 0) sred[w] = m;
        __syncthreads();
        if (tid < 8) {
            float v = sred[tid];
#pragma unroll
            for (int o = 4; o; o >>= 1) v = fmaxf(v, __shfl_xor_sync(0xffu, v, o));
            if (tid == 0) sred[0] = v;
        }
        __syncthreads();
        float M = sred[0];
        __syncthreads();
        float s = 0.f;
#pragma unroll
        for (int i = 0; i < 16; i++) s += expf(e[i] - M);
#pragma unroll
        for (int o = 16; o; o >>= 1) s += __shfl_xor_sync(0xffffffffu, s, o);
        if (lane == 0) sred[w] = s;
        __syncthreads();
        if (tid < 8) {
            float v = sred[tid];
#pragma unroll
            for (int o = 4; o; o >>= 1) v += __shfl_xor_sync(0xffu, v, o);
            if (tid == 0) sred[0] = v;
        }
        __syncthreads();
        float inv = 1.0f / sred[0];

        int colg = b & 3, rowc = b >> 2;   // rowc in [0,128): 32-row chunks
        if (tid < 32) {
            float wv = expf(g_energ[rowc * 32 + tid] - M) * inv;
            sw[tid] = wv;
            if (colg == 0) out[OUT_ATTN + rowc * 32 + tid] = wv;
        }
        __syncthreads();
        int col = colg * 256 + tid;
        const float* base = enc + (size_t)(rowc * 32) * H + col;
        float acc = 0.f;
#pragma unroll 8
        for (int j = 0; j < 32; ++j) acc += sw[j] * base[(size_t)j * H];
        atomicAdd(&g_ctx[col], acc);
    }
}

// ---------------- K4: logits (3142 blocks x 512; best measured variant) ------
__global__ __launch_bounds__(512) void k_logits(const float* __restrict__ outW,
                                                const float* __restrict__ outb,
                                                float* __restrict__ out) {
    __shared__ __align__(16) float sx[H2];
    __shared__ float srow[16];
    for (int j = threadIdx.x; j < H2; j += 512)
        sx[j] = (j < H) ? g_h1[j] : g_ctx[j - H];
    __syncthreads();
    if (blockIdx.x == 0) {
        for (int j = threadIdx.x; j < H; j += 512) out[OUT_CTX + j] = g_ctx[j];
    }
    int w = threadIdx.x >> 5, lane = threadIdx.x & 31;
    int row = blockIdx.x * LOG_ROWS_PER_BLK + w;
    float logit = -1e30f;
    if (row < V) {
        float d = warp_dot_cs<H2>(outW + (size_t)row * H2, sx, lane);
        if (lane == 0) {
            logit = d + outb[row];
            g_logits[row] = logit;
        }
    }
    if (lane == 0) srow[w] = logit;
    __syncthreads();
    if (threadIdx.x == 0) {
        float m = -1e30f;
#pragma unroll
        for (int i = 0; i < 16; i++) m = fmaxf(m, srow[i]);
        float s = 0.f;
#pragma unroll
        for (int i = 0; i < 16; i++) s += expf(srow[i] - m);
        g_pm[blockIdx.x] = m;
        g_ps[blockIdx.x] = s;
    }
}

// ---------------- K5: fused LSE + final write (50 blocks x 1024) --------------
// 1024 threads/block: max-pass loop is 4 dependent iterations (vs 7 at 512),
// 32 warps hide L2 latency, redundant partial traffic halved. Each block
// writes 1024 outputs.
__global__ __launch_bounds__(1024) void k_final(float* __restrict__ out) {
    __shared__ float sred[32];
    int tid = threadIdx.x;
    int w = tid >> 5, lane = tid & 31;
    float m = -1e30f;
    for (int i = tid; i < NB_LOGITS; i += 1024) m = fmaxf(m, g_pm[i]);
#pragma unroll
    for (int o = 16; o; o >>= 1) m = fmaxf(m, __shfl_xor_sync(0xffffffffu, m, o));
    if (lane == 0) sred[w] = m;
    __syncthreads();
    if (tid < 32) {
        float v = sred[tid];
#pragma unroll
        for (int o = 16; o; o >>= 1) v = fmaxf(v, __shfl_xor_sync(0xffffffffu, v, o));
        if (tid == 0) sred[0] = v;
    }
    __syncthreads();
    float M = sred[0];
    __syncthreads();
    float s = 0.f;
    for (int i = tid; i < NB_LOGITS; i += 1024) s += g_ps[i] * expf(g_pm[i] - M);
#pragma unroll
    for (int o = 16; o; o >>= 1) s += __shfl_xor_sync(0xffffffffu, s, o);
    if (lane == 0) sred[w] = s;
    __syncthreads();
    if (tid < 32) {
        float v = sred[tid];
#pragma unroll
        for (int o = 16; o; o >>= 1) v += __shfl_xor_sync(0xffffffffu, v, o);
        if (tid == 0) sred[0] = v;
    }
    __syncthreads();
    float L = M + logf(sred[0]);
    int idx = blockIdx.x * 1024 + tid;
    if (idx < V) out[OUT_LOGP + idx] = g_logits[idx] - L;
}

// ---------------- launch -----------------------------------------------------
extern "C" void kernel_launch(void* const* d_in, const int* in_sizes, int n_in,
                              void* d_out, int out_size) {
    const int*   tok     = (const int*)d_in[0];
    const float* lastctx = (const float*)d_in[1];
    const float* hid     = (const float*)d_in[2];
    const float* enc     = (const float*)d_in[3];
    const float* emb     = (const float*)d_in[4];
    const float* attnW   = (const float*)d_in[5];
    // d_in[6] = attn_b: softmax-invariant, dropped.
    const float* Wih0    = (const float*)d_in[7];
    const float* Whh0    = (const float*)d_in[8];
    const float* bih0    = (const float*)d_in[9];
    const float* bhh0    = (const float*)d_in[10];
    const float* Wih1    = (const float*)d_in[11];
    const float* Whh1    = (const float*)d_in[12];
    const float* bih1    = (const float*)d_in[13];
    const float* bhh1    = (const float*)d_in[14];
    const float* outW    = (const float*)d_in[15];
    const float* outb    = (const float*)d_in[16];
    float* out = (float*)d_out;

    k_gates0   <<<1152, 256>>>(tok, lastctx, hid, emb, Wih0, Whh0);
    k_gates1   <<<768, 256>>>(hid, bih0, bhh0, Wih1, bih1, Whh1, bhh1, out);
    k_attention<<<ATT_NB, 256>>>(hid, attnW, enc, out);
    k_logits   <<<NB_LOGITS, 512>>>(outW, outb, out);   // launch #4 -> profiled
    k_final    <<<(V + 1023) / 1024, 1024>>>(out);
}